// round 11
// baseline (speedup 1.0000x reference)
#include <cuda_runtime.h>
#include <math.h>

// FeedForwardQuantum v11 — 3-kernel split to decouple occupancy:
//   prep: W1 -> g_w1p pair-interleaved (global, L1-cached broadcast reads)
//   K1:   z = cos(relu(x@W1+b1)+theta) -> g_z [row][16]   (3 CTAs/SM, 24 warps)
//   K2:   out = z@W2 + b2  (stage z-dup to smem once, v10 GEMM2 inner)

#define DDIM 1024
#define QDIM 16
#define ROWS 128
#define NTH 256
#define NCH 32
#define PSTR 17
#define R2ROWS 64
#define MAXROWS 32768

typedef unsigned long long u64;

__device__ float g_w1p[DDIM * QDIM];          // pair-interleaved W1 (64KB)
__device__ float g_z[(size_t)MAXROWS * QDIM]; // z non-dup (2MB)

__device__ __forceinline__ void ffma2(u64 &d, u64 a, u64 b) {
    asm("fma.rn.f32x2 %0, %1, %2, %0;" : "+l"(d) : "l"(a), "l"(b));
}
__device__ __forceinline__ float2 unpk(u64 v) {
    float2 f;
    asm("mov.b64 {%0,%1}, %2;" : "=f"(f.x), "=f"(f.y) : "l"(v));
    return f;
}
__device__ __forceinline__ u64 pk(float x, float y) {
    u64 v;
    asm("mov.b64 %0, {%1,%2};" : "=l"(v) : "f"(x), "f"(y));
    return v;
}
__device__ __forceinline__ unsigned s2u(const void* p) {
    unsigned a;
    asm("{ .reg .u64 t; cvta.to.shared.u64 t, %1; cvt.u32.u64 %0, t; }"
        : "=r"(a) : "l"(p));
    return a;
}
#define CP8(dst, src) \
    asm volatile("cp.async.ca.shared.global [%0], [%1], 8;" :: "r"(dst), "l"(src))
#define CPCOMMIT() asm volatile("cp.async.commit_group;")
#define CPWAIT0()  asm volatile("cp.async.wait_group 0;")

// ---------------- prep: pair-interleave W1 ----------------
// g_w1p[b*32 + 2q + pp] = W1[(2b+pp)*16 + q]
__global__ void ffq_prep(const float* __restrict__ W1) {
    int o = blockIdx.x * 256 + threadIdx.x;
    if (o < DDIM * QDIM) {
        int b = o >> 5, rr = o & 31, q = rr >> 1, pp = rr & 1;
        g_w1p[o] = W1[(2 * b + pp) * QDIM + q];
    }
}

// ---------------- K1: GEMM1 + activation -> g_z ----------------
__global__ void __launch_bounds__(NTH, 3)
ffq_k1(const float* __restrict__ x, const float* __restrict__ b1,
       const float* __restrict__ theta, int nRows)
{
    extern __shared__ float sm[];
    float* xb0 = sm;                       // 128*32 = 4096 (swizzled x chunk)
    float* xb1 = xb0 + ROWS * 32;          // 4096
    float* b1s = xb1 + ROWS * 32;          // 16
    float* ths = b1s + QDIM;               // 16
    float* ps  = xb0;                      // alias: h partials post-loop

    const int tid  = threadIdx.x;
    const int row0 = blockIdx.x * ROWS;

    if (tid < QDIM) { b1s[tid] = b1[tid]; ths[tid] = theta[tid]; }

    // ---- ownership: rows p, p+64; q-half qh; d-half h (16d of 32d chunk) ----
    const int p   = tid & 63;
    const int qh  = (tid >> 6) & 1;
    const int h   = tid >> 7;
    const int key = p & 15;

    u64 acc[16];
#pragma unroll
    for (int i = 0; i < 16; i++) acc[i] = 0ULL;

    // ---- cp.async staging: thread owns rows rb+32k, float pair cols ----
    const int c4 = (tid & 7) * 4;
    const int rb = tid >> 3;
    const int e0 = c4 >> 1;
    const int keyS = rb & 15;
    const unsigned so0 = (unsigned)(2 * (e0 ^ keyS) * 4);        // bytes
    const unsigned so1 = (unsigned)(2 * ((e0 + 1) ^ keyS) * 4);
    const float* gp[4];
#pragma unroll
    for (int k = 0; k < 4; k++) {
        int gr = row0 + rb + 32 * k;
        if (gr >= nRows) gr = nRows - 1;
        gp[k] = x + (size_t)gr * DDIM + c4;
    }
    const unsigned xb0a = s2u(xb0);
    const unsigned xb1a = s2u(xb1);

    // prologue: chunk 0 -> xb0
#pragma unroll
    for (int k = 0; k < 4; k++) {
        unsigned dbase = xb0a + (unsigned)((rb + 32 * k) * 32 * 4);
        CP8(dbase + so0, gp[k]);
        CP8(dbase + so1, gp[k] + 2);
    }
    CPCOMMIT();

    for (int ch = 0; ch < NCH; ch++) {
        const float* cb = (ch & 1) ? xb1 : xb0;
        const unsigned nba = (ch & 1) ? xb0a : xb1a;

        CPWAIT0();
        __syncthreads();

        if (ch + 1 < NCH) {
            int dd = (ch + 1) * 32;
#pragma unroll
            for (int k = 0; k < 4; k++) {
                unsigned dbase = nba + (unsigned)((rb + 32 * k) * 32 * 4);
                CP8(dbase + so0, gp[k] + dd);
                CP8(dbase + so1, gp[k] + dd + 2);
            }
            CPCOMMIT();
        }

        const float* r0b = cb + p * 32;
        const float* r1b = cb + (p + 64) * 32;
        const float* wch = g_w1p + (ch * 32 + 16 * h) * QDIM + 16 * qh;
#pragma unroll
        for (int t = 0; t < 4; t++) {
            int ea = 8 * h + 2 * t;
            u64 xalo = *reinterpret_cast<const u64*>(r0b + 2 * (ea ^ key));
            u64 xahi = *reinterpret_cast<const u64*>(r0b + 2 * ((ea + 1) ^ key));
            u64 xblo = *reinterpret_cast<const u64*>(r1b + 2 * (ea ^ key));
            u64 xbhi = *reinterpret_cast<const u64*>(r1b + 2 * ((ea + 1) ^ key));
            const float* wq = wch + t * 64;            // d-pair block b0
            ulonglong2 wA0 = __ldg(reinterpret_cast<const ulonglong2*>(wq));
            ulonglong2 wA1 = __ldg(reinterpret_cast<const ulonglong2*>(wq + 4));
            ulonglong2 wA2 = __ldg(reinterpret_cast<const ulonglong2*>(wq + 8));
            ulonglong2 wA3 = __ldg(reinterpret_cast<const ulonglong2*>(wq + 12));
            ffma2(acc[0], xalo, wA0.x);  ffma2(acc[1], xalo, wA0.y);
            ffma2(acc[2], xalo, wA1.x);  ffma2(acc[3], xalo, wA1.y);
            ffma2(acc[4], xalo, wA2.x);  ffma2(acc[5], xalo, wA2.y);
            ffma2(acc[6], xalo, wA3.x);  ffma2(acc[7], xalo, wA3.y);
            ffma2(acc[8],  xblo, wA0.x); ffma2(acc[9],  xblo, wA0.y);
            ffma2(acc[10], xblo, wA1.x); ffma2(acc[11], xblo, wA1.y);
            ffma2(acc[12], xblo, wA2.x); ffma2(acc[13], xblo, wA2.y);
            ffma2(acc[14], xblo, wA3.x); ffma2(acc[15], xblo, wA3.y);
            const float* wr = wq + 32;                 // d-pair block b1
            ulonglong2 wB0 = __ldg(reinterpret_cast<const ulonglong2*>(wr));
            ulonglong2 wB1 = __ldg(reinterpret_cast<const ulonglong2*>(wr + 4));
            ulonglong2 wB2 = __ldg(reinterpret_cast<const ulonglong2*>(wr + 8));
            ulonglong2 wB3 = __ldg(reinterpret_cast<const ulonglong2*>(wr + 12));
            ffma2(acc[0], xahi, wB0.x);  ffma2(acc[1], xahi, wB0.y);
            ffma2(acc[2], xahi, wB1.x);  ffma2(acc[3], xahi, wB1.y);
            ffma2(acc[4], xahi, wB2.x);  ffma2(acc[5], xahi, wB2.y);
            ffma2(acc[6], xahi, wB3.x);  ffma2(acc[7], xahi, wB3.y);
            ffma2(acc[8],  xbhi, wB0.x); ffma2(acc[9],  xbhi, wB0.y);
            ffma2(acc[10], xbhi, wB1.x); ffma2(acc[11], xbhi, wB1.y);
            ffma2(acc[12], xbhi, wB2.x); ffma2(acc[13], xbhi, wB2.y);
            ffma2(acc[14], xbhi, wB3.x); ffma2(acc[15], xbhi, wB3.y);
        }
        __syncthreads();
    }

    // ---- combine d-halves, activation, z -> gmem (non-dup) ----
    float hv[16];
#pragma unroll
    for (int i = 0; i < 16; i++) {
        float2 a = unpk(acc[i]);
        hv[i] = a.x + a.y;
    }
    if (h == 1) {
#pragma unroll
        for (int j = 0; j < 8; j++) {
            ps[p * PSTR + 8 * qh + j]        = hv[j];
            ps[(p + 64) * PSTR + 8 * qh + j] = hv[8 + j];
        }
    }
    __syncthreads();
    if (h == 0) {
        float zo[16];
#pragma unroll
        for (int j = 0; j < 8; j++) {
            int q = 8 * qh + j;
            float v0 = hv[j] + ps[p * PSTR + q] + b1s[q];
            v0 = fmaxf(v0, 0.0f) + ths[q];
            zo[j] = __cosf(v0);
            float v1 = hv[8 + j] + ps[(p + 64) * PSTR + q] + b1s[q];
            v1 = fmaxf(v1, 0.0f) + ths[q];
            zo[8 + j] = __cosf(v1);
        }
        int g0 = row0 + p, g1 = row0 + p + 64;
        if (g0 < nRows) {
            *reinterpret_cast<float4*>(g_z + (size_t)g0 * QDIM + 8 * qh) =
                make_float4(zo[0], zo[1], zo[2], zo[3]);
            *reinterpret_cast<float4*>(g_z + (size_t)g0 * QDIM + 8 * qh + 4) =
                make_float4(zo[4], zo[5], zo[6], zo[7]);
        }
        if (g1 < nRows) {
            *reinterpret_cast<float4*>(g_z + (size_t)g1 * QDIM + 8 * qh) =
                make_float4(zo[8], zo[9], zo[10], zo[11]);
            *reinterpret_cast<float4*>(g_z + (size_t)g1 * QDIM + 8 * qh + 4) =
                make_float4(zo[12], zo[13], zo[14], zo[15]);
        }
    }
}

// ---------------- K2: out = z@W2 + b2 ----------------
__global__ void __launch_bounds__(NTH, 2)
ffq_k2(const float* __restrict__ W2, const float* __restrict__ b2,
       float* __restrict__ out, int nRows)
{
    __shared__ float zar[R2ROWS * 32];     // 8KB, z duplicated

    const int tid  = threadIdx.x;
    const int row0 = blockIdx.x * R2ROWS;

    // ---- one-shot stage: g_z[64 rows][16] -> zar dup pairs ----
    {
        int r  = tid >> 2;                 // 0..63
        int qg = tid & 3;                  // q group of 4
        int gr = row0 + r;
        if (gr >= nRows) gr = nRows - 1;
        float4 zq = *reinterpret_cast<const float4*>(g_z + (size_t)gr * QDIM + 4 * qg);
        u64* dst = reinterpret_cast<u64*>(zar + r * 32 + 8 * qg);
        dst[0] = pk(zq.x, zq.x);
        dst[1] = pk(zq.y, zq.y);
        dst[2] = pk(zq.z, zq.z);
        dst[3] = pk(zq.w, zq.w);
    }
    __syncthreads();

    // ---- GEMM2 (v10 inner): W2 in regs, broadcast z-LDS, 4-row unroll ----
    const int dcol = 4 * tid;
    ulonglong2 w2r[QDIM];
#pragma unroll
    for (int q = 0; q < QDIM; q++)
        w2r[q] = *reinterpret_cast<const ulonglong2*>(W2 + q * DDIM + dcol);

    float4 b2v = *reinterpret_cast<const float4*>(b2 + dcol);
    const u64 b2p0 = pk(b2v.x, b2v.y);
    const u64 b2p1 = pk(b2v.z, b2v.w);

    for (int rr = 0; rr < R2ROWS; rr += 4) {
        u64 a0 = b2p0, a1 = b2p1, c0 = b2p0, c1 = b2p1;
        u64 e0a = b2p0, e1a = b2p1, f0 = b2p0, f1 = b2p1;
        const float* z0 = zar + rr * 32;
        const float* z1 = z0 + 32;
        const float* z2 = z1 + 32;
        const float* z3 = z2 + 32;
        ulonglong2 zd0[4], zd1[4], zd2[4], zd3[4];
        // octet 1: floats 8m..8m+3  -> q = 4m, 4m+1
#pragma unroll
        for (int m = 0; m < 4; m++) {
            zd0[m] = *reinterpret_cast<const ulonglong2*>(z0 + 8 * m);
            zd1[m] = *reinterpret_cast<const ulonglong2*>(z1 + 8 * m);
            zd2[m] = *reinterpret_cast<const ulonglong2*>(z2 + 8 * m);
            zd3[m] = *reinterpret_cast<const ulonglong2*>(z3 + 8 * m);
        }
#pragma unroll
        for (int m = 0; m < 4; m++) {
            ffma2(a0, zd0[m].x, w2r[4 * m].x);      ffma2(a1, zd0[m].x, w2r[4 * m].y);
            ffma2(a0, zd0[m].y, w2r[4 * m + 1].x);  ffma2(a1, zd0[m].y, w2r[4 * m + 1].y);
            ffma2(c0, zd1[m].x, w2r[4 * m].x);      ffma2(c1, zd1[m].x, w2r[4 * m].y);
            ffma2(c0, zd1[m].y, w2r[4 * m + 1].x);  ffma2(c1, zd1[m].y, w2r[4 * m + 1].y);
            ffma2(e0a, zd2[m].x, w2r[4 * m].x);     ffma2(e1a, zd2[m].x, w2r[4 * m].y);
            ffma2(e0a, zd2[m].y, w2r[4 * m + 1].x); ffma2(e1a, zd2[m].y, w2r[4 * m + 1].y);
            ffma2(f0, zd3[m].x, w2r[4 * m].x);      ffma2(f1, zd3[m].x, w2r[4 * m].y);
            ffma2(f0, zd3[m].y, w2r[4 * m + 1].x);  ffma2(f1, zd3[m].y, w2r[4 * m + 1].y);
        }
        // octet 2: floats 8m+4..8m+7 -> q = 4m+2, 4m+3
#pragma unroll
        for (int m = 0; m < 4; m++) {
            zd0[m] = *reinterpret_cast<const ulonglong2*>(z0 + 8 * m + 4);
            zd1[m] = *reinterpret_cast<const ulonglong2*>(z1 + 8 * m + 4);
            zd2[m] = *reinterpret_cast<const ulonglong2*>(z2 + 8 * m + 4);
            zd3[m] = *reinterpret_cast<const ulonglong2*>(z3 + 8 * m + 4);
        }
#pragma unroll
        for (int m = 0; m < 4; m++) {
            ffma2(a0, zd0[m].x, w2r[4 * m + 2].x);  ffma2(a1, zd0[m].x, w2r[4 * m + 2].y);
            ffma2(a0, zd0[m].y, w2r[4 * m + 3].x);  ffma2(a1, zd0[m].y, w2r[4 * m + 3].y);
            ffma2(c0, zd1[m].x, w2r[4 * m + 2].x);  ffma2(c1, zd1[m].x, w2r[4 * m + 2].y);
            ffma2(c0, zd1[m].y, w2r[4 * m + 3].x);  ffma2(c1, zd1[m].y, w2r[4 * m + 3].y);
            ffma2(e0a, zd2[m].x, w2r[4 * m + 2].x); ffma2(e1a, zd2[m].x, w2r[4 * m + 2].y);
            ffma2(e0a, zd2[m].y, w2r[4 * m + 3].x); ffma2(e1a, zd2[m].y, w2r[4 * m + 3].y);
            ffma2(f0, zd3[m].x, w2r[4 * m + 2].x);  ffma2(f1, zd3[m].x, w2r[4 * m + 2].y);
            ffma2(f0, zd3[m].y, w2r[4 * m + 3].x);  ffma2(f1, zd3[m].y, w2r[4 * m + 3].y);
        }

        int go = row0 + rr;
        float2 lo, hi;
        if (go < nRows) {
            lo = unpk(a0); hi = unpk(a1);
            *reinterpret_cast<float4*>(out + (size_t)go * DDIM + dcol) =
                make_float4(lo.x, lo.y, hi.x, hi.y);
        }
        if (go + 1 < nRows) {
            lo = unpk(c0); hi = unpk(c1);
            *reinterpret_cast<float4*>(out + (size_t)(go + 1) * DDIM + dcol) =
                make_float4(lo.x, lo.y, hi.x, hi.y);
        }
        if (go + 2 < nRows) {
            lo = unpk(e0a); hi = unpk(e1a);
            *reinterpret_cast<float4*>(out + (size_t)(go + 2) * DDIM + dcol) =
                make_float4(lo.x, lo.y, hi.x, hi.y);
        }
        if (go + 3 < nRows) {
            lo = unpk(f0); hi = unpk(f1);
            *reinterpret_cast<float4*>(out + (size_t)(go + 3) * DDIM + dcol) =
                make_float4(lo.x, lo.y, hi.x, hi.y);
        }
    }
}

extern "C" void kernel_launch(void* const* d_in, const int* in_sizes, int n_in,
                              void* d_out, int out_size) {
    const float* x     = (const float*)d_in[0];
    const float* W1    = (const float*)d_in[1];
    const float* b1    = (const float*)d_in[2];
    const float* theta = (const float*)d_in[3];
    const float* W2    = (const float*)d_in[4];
    const float* b2    = (const float*)d_in[5];
    float* out = (float*)d_out;

    int nRows = in_sizes[0] / DDIM;                    // 32768
    int grid1 = (nRows + ROWS - 1) / ROWS;             // 256
    int grid2 = (nRows + R2ROWS - 1) / R2ROWS;         // 512

    size_t smem1 = (size_t)(2 * ROWS * 32 + 2 * QDIM) * sizeof(float);  // ~32.9KB

    ffq_prep<<<(DDIM * QDIM + 255) / 256, 256>>>(W1);
    ffq_k1<<<grid1, NTH, smem1>>>(x, b1, theta, nRows);
    ffq_k2<<<grid2, NTH>>>(W2, b2, out, nRows);
}

// round 13
// speedup vs baseline: 1.3621x; 1.3621x over previous
#include <cuda_runtime.h>
#include <cuda_bf16.h>
#include <math.h>
#include <stdint.h>

// FeedForwardQuantum v13 — GEMM1 via mma.sync (HMMA bf16, hi/lo split),
// GEMM2 scalar (v9-verified). tcgen05 unavailable (harness builds compute_103).
//   out = cos(relu(x@W1 + b1) + theta) @ W2 + b2
// GEMM1: D[128,32] = (x_hi + x_lo) @ [W1_hi | W1_lo] via m16n8k8 bf16 MMAs,
//        h[q] = D[:,q] + D[:,16+q]  (exact split-product reconstruction).
// Per-warp 16 rows; A interleaved (hi,lo) kpairs in smem (LDS.64 direct frags);
// B repacked [ks][n8][kp][nt] so one LDS.128 yields 4 n-tile fragments.

#define DDIM 1024
#define QDIM 16
#define ROWS 128
#define NTH  256
#define NCHK 32
#define ASTR 36          // u32 per A row: 16 kpairs x2 (hi,lo) + pad
#define ZSTR 36

typedef unsigned long long u64;
typedef unsigned int u32;

__device__ __forceinline__ void ffma2(u64 &d, u64 a, u64 b) {
    asm("fma.rn.f32x2 %0, %1, %2, %0;" : "+l"(d) : "l"(a), "l"(b));
}
__device__ __forceinline__ float2 unpk(u64 v) {
    float2 f; asm("mov.b64 {%0,%1}, %2;" : "=f"(f.x), "=f"(f.y) : "l"(v)); return f;
}
__device__ __forceinline__ u64 pk(float x, float y) {
    u64 v; asm("mov.b64 %0, {%1,%2};" : "=l"(v) : "f"(x), "f"(y)); return v;
}
// u32 = {lo16 = bf16(a), hi16 = bf16(b)}  (fragment order: lo = element k, hi = k+1)
__device__ __forceinline__ u32 pkbf(float a, float b) {
    u32 r; asm("cvt.rn.bf16x2.f32 %0, %1, %2;" : "=r"(r) : "f"(b), "f"(a)); return r;
}
__device__ __forceinline__ float bflo(u32 u) { return __uint_as_float(u << 16); }
__device__ __forceinline__ float bfhi(u32 u) { return __uint_as_float(u & 0xFFFF0000u); }

__device__ __forceinline__ void mma8(float* d, u32 a0, u32 a1, u32 b) {
    asm("mma.sync.aligned.m16n8k8.row.col.f32.bf16.bf16.f32 "
        "{%0,%1,%2,%3}, {%4,%5}, {%6}, {%0,%1,%2,%3};"
        : "+f"(d[0]), "+f"(d[1]), "+f"(d[2]), "+f"(d[3])
        : "r"(a0), "r"(a1), "r"(b));
}

__global__ void __launch_bounds__(NTH, 2)
ffq_v13(const float* __restrict__ x, const float* __restrict__ W1,
        const float* __restrict__ b1, const float* __restrict__ theta,
        const float* __restrict__ W2, const float* __restrict__ b2,
        float* __restrict__ out, int nRows)
{
    extern __shared__ u32 smu[];
    u32* Bp = smu;                          // 128ks x 8n8 x 4kp x 4nt = 16384 u32
    u32* A0 = smu + 16384;                  // 128 x 36 = 4608 u32
    u32* A1 = A0 + ROWS * ASTR;             // 4608 u32
    float* b1s = (float*)(A1 + ROWS * ASTR);// 16
    float* ths = b1s + QDIM;                // 16
    float* zar = (float*)A0;                // alias post-loop (18KB = A0 exactly)

    const int tid  = threadIdx.x;
    const int row0 = blockIdx.x * ROWS;

    if (tid < QDIM) { b1s[tid] = b1[tid]; ths[tid] = theta[tid]; }

    // ---- stage B: W1 -> bf16 hi/lo fragments, layout [ks][n8][kp][nt] ----
    // global n: q (hi, nt=q/8) and 16+q (lo, nt=2+q/8); n8 = q%8.
    for (int i = tid; i < 8192; i += NTH) {
        int kp  = i & 3;
        int q   = (i >> 2) & 15;
        int ksg = i >> 6;                   // 0..127
        int k0  = ksg * 8 + kp * 2;
        float w0 = W1[(size_t)k0 * QDIM + q];
        float w1 = W1[(size_t)(k0 + 1) * QDIM + q];
        u32 hi = pkbf(w0, w1);
        u32 lo = pkbf(w0 - bflo(hi), w1 - bfhi(hi));
        int base = ksg * 128 + (q & 7) * 16 + kp * 4 + (q >> 3);
        Bp[base]     = hi;
        Bp[base + 2] = lo;
    }

    // ---- x staging ownership: row = tid>>1, k-half hh = tid&1 (16 floats) ----
    const int srow = tid >> 1;
    const int hh   = tid & 1;
    int gr = row0 + srow; if (gr >= nRows) gr = nRows - 1;
    const float* gx = x + (size_t)gr * DDIM + 16 * hh;

    // prologue: chunk 0 -> A0
    {
        float4 pf[4];
#pragma unroll
        for (int j = 0; j < 4; j++) pf[j] = *(const float4*)(gx + 4 * j);
        u32* dst = A0 + srow * ASTR + 16 * hh;
#pragma unroll
        for (int j = 0; j < 4; j++) {
            u32 h0 = pkbf(pf[j].x, pf[j].y);
            u32 l0 = pkbf(pf[j].x - bflo(h0), pf[j].y - bfhi(h0));
            u32 h1 = pkbf(pf[j].z, pf[j].w);
            u32 l1 = pkbf(pf[j].z - bflo(h1), pf[j].w - bfhi(h1));
            *(uint4*)(dst + 4 * j) = make_uint4(h0, l0, h1, l1);
        }
    }

    // ---- MMA main loop ----
    const int wid  = tid >> 5;
    const int lane = tid & 31;
    const int g    = lane >> 2;             // row group 0..7
    const int c    = lane & 3;              // k-pair / col-pair 0..3
    const u32 aoff0 = (u32)((16 * wid + g) * ASTR);
    const u32 aoff1 = aoff0 + 8 * ASTR;

    float d[4][4];
#pragma unroll
    for (int n = 0; n < 4; n++)
#pragma unroll
        for (int j = 0; j < 4; j++) d[n][j] = 0.0f;

    for (int ch = 0; ch < NCHK; ch++) {
        __syncthreads();                    // chunk ch staged; other buffer free
        const u32* cur = (ch & 1) ? A1 : A0;
        u32*       nxt = (ch & 1) ? A0 : A1;

        float4 pf[4];
        if (ch + 1 < NCHK) {
            int dd = (ch + 1) * 32;
#pragma unroll
            for (int j = 0; j < 4; j++)
                pf[j] = *(const float4*)(gx + dd + 4 * j);
        }

#pragma unroll
        for (int ks = 0; ks < 4; ks++) {
            int kloc = (ks * 4 + c) * 2;
            u64 av0 = *(const u64*)(cur + aoff0 + kloc);   // lo32=hi-frag, hi32=lo-frag
            u64 av1 = *(const u64*)(cur + aoff1 + kloc);
            u32 a0h = (u32)av0,  a0l = (u32)(av0 >> 32);
            u32 a1h = (u32)av1,  a1l = (u32)(av1 >> 32);
            int ksg = ch * 4 + ks;
            uint4 b = *(const uint4*)(Bp + ksg * 128 + g * 16 + c * 4);
            mma8(d[0], a0h, a1h, b.x);
            mma8(d[1], a0h, a1h, b.y);
            mma8(d[2], a0h, a1h, b.z);
            mma8(d[3], a0h, a1h, b.w);
            mma8(d[0], a0l, a1l, b.x);
            mma8(d[1], a0l, a1l, b.y);
            mma8(d[2], a0l, a1l, b.z);
            mma8(d[3], a0l, a1l, b.w);
        }

        if (ch + 1 < NCHK) {
            u32* dst = nxt + srow * ASTR + 16 * hh;
#pragma unroll
            for (int j = 0; j < 4; j++) {
                u32 h0 = pkbf(pf[j].x, pf[j].y);
                u32 l0 = pkbf(pf[j].x - bflo(h0), pf[j].y - bfhi(h0));
                u32 h1 = pkbf(pf[j].z, pf[j].w);
                u32 l1 = pkbf(pf[j].z - bflo(h1), pf[j].w - bfhi(h1));
                *(uint4*)(dst + 4 * j) = make_uint4(h0, l0, h1, l1);
            }
        }
    }
    __syncthreads();                        // all MMA reads of A0/A1 done

    // ---- epilogue: h = D[:,q] + D[:,16+q] + b1 -> relu -> +theta -> cos ----
    // thread owns rows r0 = 16*wid+g, r1 = r0+8; q in {2c, 2c+1, 8+2c, 8+2c+1}
    {
        int r0 = 16 * wid + g;
        int r1 = r0 + 8;
        int qa = 2 * c, qc = 8 + 2 * c;
        float za0, za1, zb0, zb1;
#pragma unroll
        for (int rr = 0; rr < 2; rr++) {
            int j0 = rr * 2;                // D reg index: rows g (+0,1), g+8 (+2,3)
            int row = rr ? r1 : r0;
            float h0 = d[0][j0]     + d[2][j0]     + b1s[qa];
            float h1 = d[0][j0 + 1] + d[2][j0 + 1] + b1s[qa + 1];
            float h2 = d[1][j0]     + d[3][j0]     + b1s[qc];
            float h3 = d[1][j0 + 1] + d[3][j0 + 1] + b1s[qc + 1];
            h0 = fmaxf(h0, 0.0f) + ths[qa];
            h1 = fmaxf(h1, 0.0f) + ths[qa + 1];
            h2 = fmaxf(h2, 0.0f) + ths[qc];
            h3 = fmaxf(h3, 0.0f) + ths[qc + 1];
            za0 = __cosf(h0); za1 = __cosf(h1);
            zb0 = __cosf(h2); zb1 = __cosf(h3);
            *(float4*)(zar + row * ZSTR + 4 * c)      = make_float4(za0, za0, za1, za1);
            *(float4*)(zar + row * ZSTR + 16 + 4 * c) = make_float4(zb0, zb0, zb1, zb1);
        }
    }
    __syncthreads();

    // ---- GEMM2 (v9-verified): W2 in regs, z dup broadcast LDS, 4-row unroll ----
    const int dcol = 4 * tid;
    ulonglong2 w2r[QDIM];
#pragma unroll
    for (int q = 0; q < QDIM; q++)
        w2r[q] = *reinterpret_cast<const ulonglong2*>(W2 + q * DDIM + dcol);

    float4 b2v = *reinterpret_cast<const float4*>(b2 + dcol);
    const u64 b2p0 = pk(b2v.x, b2v.y);
    const u64 b2p1 = pk(b2v.z, b2v.w);

    for (int rr = 0; rr < ROWS; rr += 4) {
        u64 a0 = b2p0, a1 = b2p1, c0 = b2p0, c1 = b2p1;
        u64 e0 = b2p0, e1 = b2p1, f0 = b2p0, f1 = b2p1;
        const float* z0 = zar + rr * ZSTR;
        const float* z1 = z0 + ZSTR;
        const float* z2 = z1 + ZSTR;
        const float* z3 = z2 + ZSTR;
        ulonglong2 zd0[4], zd1[4], zd2[4], zd3[4];
        // octet 1: floats 8m..8m+3 -> q = 4m, 4m+1
#pragma unroll
        for (int m = 0; m < 4; m++) {
            zd0[m] = *reinterpret_cast<const ulonglong2*>(z0 + 8 * m);
            zd1[m] = *reinterpret_cast<const ulonglong2*>(z1 + 8 * m);
            zd2[m] = *reinterpret_cast<const ulonglong2*>(z2 + 8 * m);
            zd3[m] = *reinterpret_cast<const ulonglong2*>(z3 + 8 * m);
        }
#pragma unroll
        for (int m = 0; m < 4; m++) {
            ffma2(a0, zd0[m].x, w2r[4 * m].x);     ffma2(a1, zd0[m].x, w2r[4 * m].y);
            ffma2(a0, zd0[m].y, w2r[4 * m + 1].x); ffma2(a1, zd0[m].y, w2r[4 * m + 1].y);
            ffma2(c0, zd1[m].x, w2r[4 * m].x);     ffma2(c1, zd1[m].x, w2r[4 * m].y);
            ffma2(c0, zd1[m].y, w2r[4 * m + 1].x); ffma2(c1, zd1[m].y, w2r[4 * m + 1].y);
            ffma2(e0, zd2[m].x, w2r[4 * m].x);     ffma2(e1, zd2[m].x, w2r[4 * m].y);
            ffma2(e0, zd2[m].y, w2r[4 * m + 1].x); ffma2(e1, zd2[m].y, w2r[4 * m + 1].y);
            ffma2(f0, zd3[m].x, w2r[4 * m].x);     ffma2(f1, zd3[m].x, w2r[4 * m].y);
            ffma2(f0, zd3[m].y, w2r[4 * m + 1].x); ffma2(f1, zd3[m].y, w2r[4 * m + 1].y);
        }
        // octet 2: floats 8m+4..8m+7 -> q = 4m+2, 4m+3
#pragma unroll
        for (int m = 0; m < 4; m++) {
            zd0[m] = *reinterpret_cast<const ulonglong2*>(z0 + 8 * m + 4);
            zd1[m] = *reinterpret_cast<const ulonglong2*>(z1 + 8 * m + 4);
            zd2[m] = *reinterpret_cast<const ulonglong2*>(z2 + 8 * m + 4);
            zd3[m] = *reinterpret_cast<const ulonglong2*>(z3 + 8 * m + 4);
        }
#pragma unroll
        for (int m = 0; m < 4; m++) {
            ffma2(a0, zd0[m].x, w2r[4 * m + 2].x); ffma2(a1, zd0[m].x, w2r[4 * m + 2].y);
            ffma2(a0, zd0[m].y, w2r[4 * m + 3].x); ffma2(a1, zd0[m].y, w2r[4 * m + 3].y);
            ffma2(c0, zd1[m].x, w2r[4 * m + 2].x); ffma2(c1, zd1[m].x, w2r[4 * m + 2].y);
            ffma2(c0, zd1[m].y, w2r[4 * m + 3].x); ffma2(c1, zd1[m].y, w2r[4 * m + 3].y);
            ffma2(e0, zd2[m].x, w2r[4 * m + 2].x); ffma2(e1, zd2[m].x, w2r[4 * m + 2].y);
            ffma2(e0, zd2[m].y, w2r[4 * m + 3].x); ffma2(e1, zd2[m].y, w2r[4 * m + 3].y);
            ffma2(f0, zd3[m].x, w2r[4 * m + 2].x); ffma2(f1, zd3[m].x, w2r[4 * m + 2].y);
            ffma2(f0, zd3[m].y, w2r[4 * m + 3].x); ffma2(f1, zd3[m].y, w2r[4 * m + 3].y);
        }

        int go = row0 + rr;
        float2 lo2, hi2;
        if (go < nRows) {
            lo2 = unpk(a0); hi2 = unpk(a1);
            *reinterpret_cast<float4*>(out + (size_t)go * DDIM + dcol) =
                make_float4(lo2.x, lo2.y, hi2.x, hi2.y);
        }
        if (go + 1 < nRows) {
            lo2 = unpk(c0); hi2 = unpk(c1);
            *reinterpret_cast<float4*>(out + (size_t)(go + 1) * DDIM + dcol) =
                make_float4(lo2.x, lo2.y, hi2.x, hi2.y);
        }
        if (go + 2 < nRows) {
            lo2 = unpk(e0); hi2 = unpk(e1);
            *reinterpret_cast<float4*>(out + (size_t)(go + 2) * DDIM + dcol) =
                make_float4(lo2.x, lo2.y, hi2.x, hi2.y);
        }
        if (go + 3 < nRows) {
            lo2 = unpk(f0); hi2 = unpk(f1);
            *reinterpret_cast<float4*>(out + (size_t)(go + 3) * DDIM + dcol) =
                make_float4(lo2.x, lo2.y, hi2.x, hi2.y);
        }
    }
}

extern "C" void kernel_launch(void* const* d_in, const int* in_sizes, int n_in,
                              void* d_out, int out_size) {
    const float* x     = (const float*)d_in[0];
    const float* W1    = (const float*)d_in[1];
    const float* b1    = (const float*)d_in[2];
    const float* theta = (const float*)d_in[3];
    const float* W2    = (const float*)d_in[4];
    const float* b2    = (const float*)d_in[5];
    float* out = (float*)d_out;

    int nRows = in_sizes[0] / DDIM;                    // 32768
    int grid  = (nRows + ROWS - 1) / ROWS;             // 256

    // B 16384 u32 + 2 A buffers (2*4608) + b1s/ths 32 = 25632 u32 ≈ 100.1KB
    size_t smem = (size_t)(16384 + 2 * ROWS * ASTR + 2 * QDIM) * sizeof(u32);
    static int attr_set = 0;
    if (!attr_set) {
        cudaFuncSetAttribute(ffq_v13, cudaFuncAttributeMaxDynamicSharedMemorySize,
                             (int)smem);
        attr_set = 1;
    }

    ffq_v13<<<grid, NTH, smem>>>(x, W1, b1, theta, W2, b2, out, nRows);
}